// round 10
// baseline (speedup 1.0000x reference)
#include <cuda_runtime.h>
#include <cuda_bf16.h>
#include <cstdint>

// EdgeConv: message MLP over edges + mean-aggregate + update MLP + residual.
// R10: aggregate h (post-ReLU hidden) instead of messages; since aggregation
// and W2 are linear, W2 folds into the node-update weights:
//   Wu2 = [Wu_top ; W2 @ Wu_bot],  b2u = b2 @ Wu_bot
// Edge path: gather P[src],Q[dst],ea -> ea@W1c (8 MMA, hoisted B frags)
// -> +P+Q+b1, ReLU -> scatter h. GEMM2 and its epilogue stage are gone.

#define ND      64
#define EDIM    16
#define HID     64
#define TILE_N  64
#define MAXN    100000

#define LDIN_H  184   // bf16 In row stride (368B)
#define LDW_H   88    // bf16 weight row stride (176B)
#define LDX_H   72    // pq kernel x-tile row stride (144B)
#define LDSC_F  92    // f32 view of In row stride

// Row layout (bf16 els): [0,16) ea | [16,80) P[src] | [80,144) Q[dst]
// | [144,176) ea f32 staging | [176,184) pad.

__device__ float         g_agg[(size_t)MAXN * HID];   // sum of h per dst
__device__ float         g_cnt[MAXN];
__device__ __nv_bfloat16 g_P[(size_t)MAXN * HID];
__device__ __nv_bfloat16 g_Q[(size_t)MAXN * HID];
__device__ float         g_Wu2[2 * ND * HID];         // folded update weights
__device__ float         g_b2u[HID];                  // b2 @ Wu_bot

static __device__ __forceinline__ uint32_t s2u(const void* p) {
    return (uint32_t)__cvta_generic_to_shared(p);
}
static __device__ __forceinline__ void cp16(uint32_t dst, const void* src) {
    asm volatile("cp.async.cg.shared.global [%0], [%1], 16;" :: "r"(dst), "l"(src));
}
static __device__ __forceinline__ void ldsm_x4(uint32_t addr, uint32_t& r0,
                                               uint32_t& r1, uint32_t& r2,
                                               uint32_t& r3) {
    asm volatile("ldmatrix.sync.aligned.m8n8.x4.shared.b16 {%0,%1,%2,%3}, [%4];"
                 : "=r"(r0), "=r"(r1), "=r"(r2), "=r"(r3) : "r"(addr));
}
static __device__ __forceinline__ void ldsm_x4t(uint32_t addr, uint32_t& r0,
                                                uint32_t& r1, uint32_t& r2,
                                                uint32_t& r3) {
    asm volatile("ldmatrix.sync.aligned.m8n8.x4.trans.shared.b16 {%0,%1,%2,%3}, [%4];"
                 : "=r"(r0), "=r"(r1), "=r"(r2), "=r"(r3) : "r"(addr));
}
static __device__ __forceinline__ void mma16816(float* c, uint32_t a0, uint32_t a1,
                                                uint32_t a2, uint32_t a3,
                                                uint32_t b0, uint32_t b1) {
    asm volatile(
        "mma.sync.aligned.m16n8k16.row.col.f32.bf16.bf16.f32 "
        "{%0,%1,%2,%3}, {%4,%5,%6,%7}, {%8,%9}, {%0,%1,%2,%3};"
        : "+f"(c[0]), "+f"(c[1]), "+f"(c[2]), "+f"(c[3])
        : "r"(a0), "r"(a1), "r"(a2), "r"(a3), "r"(b0), "r"(b1));
}
static __device__ __forceinline__ uint32_t cvt2(float lo, float hi) {
    __nv_bfloat162 p = __floats2bfloat162_rn(lo, hi);
    return *reinterpret_cast<uint32_t*>(&p);
}

// ---------------------------------------------------------------------------
__global__ void zero_kernel(int N) {
    long long i = (long long)blockIdx.x * blockDim.x + threadIdx.x;
    long long stride = (long long)gridDim.x * blockDim.x;
    float4* a4 = reinterpret_cast<float4*>(g_agg);
    long long n4 = (long long)N * (HID / 4);
    float4 z = make_float4(0.f, 0.f, 0.f, 0.f);
    for (long long j = i; j < n4; j += stride) a4[j] = z;
    for (long long j = i; j < N; j += stride) g_cnt[j] = 0.f;
}

// ---------------------------------------------------------------------------
// w2u_kernel: g_Wu2 top = Wu rows [0,64); bottom = W2 @ Wu rows [64,128);
// g_b2u = b2 @ Wu rows [64,128). All fp32.
// ---------------------------------------------------------------------------
__global__ void w2u_kernel(const float* __restrict__ W2,
                           const float* __restrict__ Wu,
                           const float* __restrict__ b2) {
    int i = blockIdx.x * blockDim.x + threadIdx.x;
    if (i < ND * HID) {
        g_Wu2[i] = Wu[i];
    } else if (i < 2 * ND * HID) {
        int r = i - ND * HID;
        int j = r >> 6, n = r & 63;
        float s = 0.f;
        for (int m = 0; m < HID; m++)
            s += W2[j * HID + m] * Wu[(ND + m) * HID + n];
        g_Wu2[i] = s;
    } else if (i < 2 * ND * HID + HID) {
        int n = i - 2 * ND * HID;
        float s = 0.f;
        for (int m = 0; m < HID; m++)
            s += b2[m] * Wu[(ND + m) * HID + n];
        g_b2u[n] = s;
    }
}

// ---------------------------------------------------------------------------
// pq_kernel: P = x @ W1[0:64], Q = x @ W1[64:128], bf16 outputs.
// ---------------------------------------------------------------------------
__global__ void __launch_bounds__(256)
pq_kernel(const float* __restrict__ x, const float* __restrict__ W1,
          int N, int ntiles) {
    extern __shared__ __align__(16) char smq[];
    __nv_bfloat16* sWa = reinterpret_cast<__nv_bfloat16*>(smq);
    __nv_bfloat16* sWb = sWa + 64 * LDW_H;
    __nv_bfloat16* sX  = sWb + 64 * LDW_H;

    const int tid = threadIdx.x;
    for (int i = tid; i < 64 * 64; i += 256) {
        int k = i >> 6, n = i & 63;
        sWa[k * LDW_H + n] = __float2bfloat16_rn(W1[k * HID + n]);
        sWb[k * LDW_H + n] = __float2bfloat16_rn(W1[(64 + k) * HID + n]);
    }
    __syncthreads();

    const int wid = tid >> 5, lane = tid & 31;
    const int gq = lane >> 2, tq = lane & 3;
    const int el = lane >> 1, part = lane & 1;

    __nv_bfloat16* myX = sX + wid * 16 * LDX_H;
    const uint32_t xBase = s2u(myX) + (((lane & 15) * LDX_H) + 8 * (lane >> 4)) * 2;
    const uint32_t waBase = s2u(sWa) + (((lane & 15) * LDW_H) + 8 * (lane >> 4)) * 2;
    const uint32_t wbBase = s2u(sWb) + (((lane & 15) * LDW_H) + 8 * (lane >> 4)) * 2;

    for (int t = blockIdx.x * 8 + wid; t < ntiles; t += gridDim.x * 8) {
        const int n0 = t * 16;
        {
            const int n = n0 + el;
            uint4* dst = reinterpret_cast<uint4*>(myX + el * LDX_H + part * 32);
            if (n < N) {
                const float4* xr = reinterpret_cast<const float4*>(
                    x + (size_t)n * ND) + part * 8;
#pragma unroll
                for (int i = 0; i < 4; i++) {
                    float4 a = xr[2 * i], b = xr[2 * i + 1];
                    uint4 u;
                    u.x = cvt2(a.x, a.y); u.y = cvt2(a.z, a.w);
                    u.z = cvt2(b.x, b.y); u.w = cvt2(b.z, b.w);
                    dst[i] = u;
                }
            } else {
                uint4 z = make_uint4(0, 0, 0, 0);
#pragma unroll
                for (int i = 0; i < 4; i++) dst[i] = z;
            }
        }
        __syncwarp();

        float accP[8][4], accQ[8][4];
#pragma unroll
        for (int j = 0; j < 8; j++)
#pragma unroll
            for (int q = 0; q < 4; q++) { accP[j][q] = 0.f; accQ[j][q] = 0.f; }

#pragma unroll
        for (int k = 0; k < 4; k++) {
            uint32_t a0, a1, a2, a3;
            ldsm_x4(xBase + k * 32, a0, a1, a2, a3);
#pragma unroll
            for (int nb = 0; nb < 4; nb++) {
                uint32_t p0, p1, p2, p3;
                ldsm_x4t(waBase + (k * 16 * LDW_H + nb * 16) * 2, p0, p1, p2, p3);
                mma16816(accP[2 * nb],     a0, a1, a2, a3, p0, p1);
                mma16816(accP[2 * nb + 1], a0, a1, a2, a3, p2, p3);
                ldsm_x4t(wbBase + (k * 16 * LDW_H + nb * 16) * 2, p0, p1, p2, p3);
                mma16816(accQ[2 * nb],     a0, a1, a2, a3, p0, p1);
                mma16816(accQ[2 * nb + 1], a0, a1, a2, a3, p2, p3);
            }
        }

        const int r0n = n0 + gq, r1n = n0 + gq + 8;
#pragma unroll
        for (int j = 0; j < 8; j++) {
            const int c = 8 * j + 2 * tq;
            if (r0n < N) {
                *reinterpret_cast<uint32_t*>(g_P + (size_t)r0n * HID + c) =
                    cvt2(accP[j][0], accP[j][1]);
                *reinterpret_cast<uint32_t*>(g_Q + (size_t)r0n * HID + c) =
                    cvt2(accQ[j][0], accQ[j][1]);
            }
            if (r1n < N) {
                *reinterpret_cast<uint32_t*>(g_P + (size_t)r1n * HID + c) =
                    cvt2(accP[j][2], accP[j][3]);
                *reinterpret_cast<uint32_t*>(g_Q + (size_t)r1n * HID + c) =
                    cvt2(accQ[j][2], accQ[j][3]);
            }
        }
        __syncwarp();
    }
}

// ---------------------------------------------------------------------------
static __device__ __forceinline__ void issue_stage(
    __nv_bfloat16* myIn, uint32_t inU32, int* myDst, int stage, int tile,
    int myIdx, const float* __restrict__ ea, int E, int lane) {
    const int el = lane >> 1;
    const int part = lane & 1;
    const int e = tile * 16 + el;
    const uint32_t rb = inU32 + (uint32_t)(stage * 16 + el) * (LDIN_H * 2);
    if (e < E) {
        const char* ap = reinterpret_cast<const char*>(ea + (size_t)e * EDIM);
        if (part == 0) {
            const char* ps = reinterpret_cast<const char*>(g_P + (size_t)myIdx * HID);
#pragma unroll
            for (int i = 0; i < 8; i++) cp16(rb + 32 + i * 16, ps + i * 16);
            cp16(rb + 288, ap);
            cp16(rb + 304, ap + 16);
        } else {
            myDst[stage * 16 + el] = myIdx;
            const char* qd = reinterpret_cast<const char*>(g_Q + (size_t)myIdx * HID);
#pragma unroll
            for (int i = 0; i < 8; i++) cp16(rb + 160 + i * 16, qd + i * 16);
            cp16(rb + 320, ap + 32);
            cp16(rb + 336, ap + 48);
        }
    } else {
        uint4 z = make_uint4(0, 0, 0, 0);
        uint4* rp4 = reinterpret_cast<uint4*>(myIn + (stage * 16 + el) * LDIN_H);
        if (part == 0) {
#pragma unroll
            for (int i = 2; i < 10; i++) rp4[i] = z;
            rp4[18] = z; rp4[19] = z;
        } else {
            myDst[stage * 16 + el] = -1;
#pragma unroll
            for (int i = 10; i < 18; i++) rp4[i] = z;
            rp4[20] = z; rp4[21] = z;
        }
    }
}

// ---------------------------------------------------------------------------
// Edge kernel: 512 threads, 16 warps, 1 CTA/SM. 2-stage cp.async pipeline.
// GEMM1 = ea(16x16)@W1c(16x64) with hoisted B frags; h = relu(+P+Q+b1);
// scatter h.
// ---------------------------------------------------------------------------
__global__ void __launch_bounds__(512, 1)
edge_kernel(const int* __restrict__ eidx, const float* __restrict__ ea,
            const float* __restrict__ W1, const float* __restrict__ b1,
            int E, int nst) {
    extern __shared__ __align__(16) char smraw[];
    __nv_bfloat16* sW1c = reinterpret_cast<__nv_bfloat16*>(smraw);      // 16*88
    __nv_bfloat16* sIn  = sW1c + 16 * LDW_H;                            // 16w*32*184
    int*           sDst = reinterpret_cast<int*>(sIn + 16 * 32 * LDIN_H); // 512

    const int tid = threadIdx.x;
    for (int i = tid; i < 16 * HID; i += 512) {
        int k = i >> 6, n = i & 63;
        sW1c[k * LDW_H + n] = __float2bfloat16_rn(W1[(128 + k) * HID + n]);
    }
    __syncthreads();

    const int wid  = tid >> 5;
    const int lane = tid & 31;
    const int gq   = lane >> 2;
    const int tq   = lane & 3;
    const int el   = lane >> 1;
    const int part = lane & 1;
    const int gw   = blockIdx.x * 16 + wid;
    const int gstride = gridDim.x * 16;

    const int* __restrict__ srcp = eidx;
    const int* __restrict__ dstp = eidx + E;
    const int* __restrict__ idxp = part ? dstp : srcp;

    __nv_bfloat16* myIn  = sIn + wid * 32 * LDIN_H;
    float*         myScr = reinterpret_cast<float*>(myIn);
    int*           myDst = sDst + wid * 32;
    const uint32_t inU32 = s2u(myIn);

    float2 bias1[8];
#pragma unroll
    for (int j = 0; j < 8; j++) {
        bias1[j].x = b1[8 * j + 2 * tq];
        bias1[j].y = b1[8 * j + 2 * tq + 1];
    }

    const uint32_t inBase  = inU32 + (((lane & 15) * LDIN_H) + 8 * (lane >> 4)) * 2;
    const uint32_t w1cBase = s2u(sW1c) + (((lane & 15) * LDW_H) + 8 * (lane >> 4)) * 2;

    // hoisted GEMM1 B fragments (loop-invariant)
    uint32_t w1f[4][4];
#pragma unroll
    for (int nb = 0; nb < 4; nb++)
        ldsm_x4t(w1cBase + (nb * 16) * 2, w1f[nb][0], w1f[nb][1],
                 w1f[nb][2], w1f[nb][3]);

    // ---- prologue ----
    {
        int e0 = gw * 16 + el;
        int idx0 = (e0 < E) ? idxp[e0] : 0;
        issue_stage(myIn, inU32, myDst, 0, gw, idx0, ea, E, lane);
    }
    asm volatile("cp.async.commit_group;" ::: "memory");
    int idxN = 0;
    {
        int tn = gw + gstride;
        int en = tn * 16 + el;
        if (tn < nst && en < E) idxN = idxp[en];
    }

    int it = 0;
    for (int t = gw; t < nst; t += gstride, it++) {
        const int s = it & 1;
        const int r0 = s * 16;
        const int tnext = t + gstride;

        if (tnext < nst)
            issue_stage(myIn, inU32, myDst, s ^ 1, tnext, idxN, ea, E, lane);
        asm volatile("cp.async.commit_group;" ::: "memory");
        {
            const int t2 = tnext + gstride;
            const int e2 = t2 * 16 + el;
            idxN = (t2 < nst && e2 < E) ? idxp[e2] : 0;
        }
        asm volatile("cp.async.wait_group 1;" ::: "memory");
        __syncwarp();

        // ---- convert staged ea f32 -> bf16 cols [0,16) ----
        {
            float* rowf = myScr + (r0 + el) * LDSC_F;
            float4 a = *reinterpret_cast<const float4*>(rowf + 72 + part * 8);
            float4 b = *reinterpret_cast<const float4*>(rowf + 76 + part * 8);
            uint4 u;
            u.x = cvt2(a.x, a.y); u.y = cvt2(a.z, a.w);
            u.z = cvt2(b.x, b.y); u.w = cvt2(b.z, b.w);
            *reinterpret_cast<uint4*>(reinterpret_cast<char*>(rowf) + part * 16) = u;
        }
        __syncwarp();

        // ---- GEMM1: ea(16x16) @ W1c(16x64) ----
        float acc[8][4];
#pragma unroll
        for (int j = 0; j < 8; j++)
#pragma unroll
            for (int q = 0; q < 4; q++) acc[j][q] = 0.f;
        {
            uint32_t a0, a1, a2, a3;
            ldsm_x4(inBase + r0 * LDIN_H * 2, a0, a1, a2, a3);
#pragma unroll
            for (int nb = 0; nb < 4; nb++) {
                mma16816(acc[2 * nb],     a0, a1, a2, a3, w1f[nb][0], w1f[nb][1]);
                mma16816(acc[2 * nb + 1], a0, a1, a2, a3, w1f[nb][2], w1f[nb][3]);
            }
        }

        // ---- h = relu(acc + P + Q + b1) into registers ----
        float2 rv0[8], rv1[8];
        {
            const __nv_bfloat16* rowA = myIn + (r0 + gq) * LDIN_H + 16;
            const __nv_bfloat16* rowB = myIn + (r0 + gq + 8) * LDIN_H + 16;
#pragma unroll
            for (int j = 0; j < 8; j++) {
                const int c = 8 * j + 2 * tq;
                float2 pA = __bfloat1622float2(
                    *reinterpret_cast<const __nv_bfloat162*>(rowA + c));
                float2 qA = __bfloat1622float2(
                    *reinterpret_cast<const __nv_bfloat162*>(rowA + 64 + c));
                float2 pB = __bfloat1622float2(
                    *reinterpret_cast<const __nv_bfloat162*>(rowB + c));
                float2 qB = __bfloat1622float2(
                    *reinterpret_cast<const __nv_bfloat162*>(rowB + 64 + c));
                rv0[j].x = fmaxf(acc[j][0] + pA.x + qA.x + bias1[j].x, 0.f);
                rv0[j].y = fmaxf(acc[j][1] + pA.y + qA.y + bias1[j].y, 0.f);
                rv1[j].x = fmaxf(acc[j][2] + pB.x + qB.x + bias1[j].x, 0.f);
                rv1[j].y = fmaxf(acc[j][3] + pB.y + qB.y + bias1[j].y, 0.f);
            }
        }
        __syncwarp();   // all P/Q reads done before scratch overwrite

        {
            float* base0 = myScr + (r0 + gq) * LDSC_F + 2 * tq;
            float* base1 = myScr + (r0 + gq + 8) * LDSC_F + 2 * tq;
#pragma unroll
            for (int j = 0; j < 8; j++) {
                *reinterpret_cast<float2*>(base0 + 8 * j) = rv0[j];
                *reinterpret_cast<float2*>(base1 + 8 * j) = rv1[j];
            }
        }
        __syncwarp();

        // ---- float4 atomic scatter of h ----
#pragma unroll
        for (int i = 0; i < 8; i++) {
            const int idx = lane + 32 * i;
            const int row = idx >> 4;
            const int c4  = idx & 15;
            const int d = myDst[r0 + row];
            if (d >= 0) {
                float4 v = *reinterpret_cast<const float4*>(
                    myScr + (r0 + row) * LDSC_F + c4 * 4);
                atomicAdd(reinterpret_cast<float4*>(
                    g_agg + (size_t)d * HID + c4 * 4), v);
            }
        }
        if (lane < 16) {
            const int d = myDst[r0 + lane];
            if (d >= 0) atomicAdd(&g_cnt[d], 1.0f);
        }
        __syncwarp();
    }
}

// ---------------------------------------------------------------------------
// Node kernel: out = x + relu([x, mean_h] @ Wu2 + bu + f*b2u), f = cnt*inv.
// ---------------------------------------------------------------------------
#define FMA16(ACC, AV, BV)                                                    \
  ACC[0][0] = fmaf(AV.x, BV.x, ACC[0][0]);                                    \
  ACC[0][1] = fmaf(AV.x, BV.y, ACC[0][1]);                                    \
  ACC[0][2] = fmaf(AV.x, BV.z, ACC[0][2]);                                    \
  ACC[0][3] = fmaf(AV.x, BV.w, ACC[0][3]);                                    \
  ACC[1][0] = fmaf(AV.y, BV.x, ACC[1][0]);                                    \
  ACC[1][1] = fmaf(AV.y, BV.y, ACC[1][1]);                                    \
  ACC[1][2] = fmaf(AV.y, BV.z, ACC[1][2]);                                    \
  ACC[1][3] = fmaf(AV.y, BV.w, ACC[1][3]);                                    \
  ACC[2][0] = fmaf(AV.z, BV.x, ACC[2][0]);                                    \
  ACC[2][1] = fmaf(AV.z, BV.y, ACC[2][1]);                                    \
  ACC[2][2] = fmaf(AV.z, BV.z, ACC[2][2]);                                    \
  ACC[2][3] = fmaf(AV.z, BV.w, ACC[2][3]);                                    \
  ACC[3][0] = fmaf(AV.w, BV.x, ACC[3][0]);                                    \
  ACC[3][1] = fmaf(AV.w, BV.y, ACC[3][1]);                                    \
  ACC[3][2] = fmaf(AV.w, BV.z, ACC[3][2]);                                    \
  ACC[3][3] = fmaf(AV.w, BV.w, ACC[3][3]);

__global__ void __launch_bounds__(256, 3)
node_kernel(const float* __restrict__ x, const float* __restrict__ bu,
            float* __restrict__ out, int N, int ntiles) {
    extern __shared__ float smn[];
    float* sWu  = smn;                     // [128][64] folded weights
    float* sIn  = sWu + 2 * ND * HID;      // [128][64]
    float* sBu  = sIn + 2 * ND * TILE_N;   // [64]
    float* sB2u = sBu + HID;               // [64]
    float* sF   = sB2u + HID;              // [64] per-node f = cnt*inv

    const int tid = threadIdx.x;
    for (int i = tid; i < 2 * ND * HID; i += 256) sWu[i] = g_Wu2[i];
    if (tid < HID) { sBu[tid] = bu[tid]; sB2u[tid] = g_b2u[tid]; }
    __syncthreads();

    const int tx = tid & 15;
    const int ty = tid >> 4;
    const int q  = tid & 3;
    const int ng = tid >> 2;

    for (int tile = blockIdx.x; tile < ntiles; tile += gridDim.x) {
        const int n0 = tile * TILE_N;
        {
            const int n = n0 + ng;
            if (n < N) {
                const float cnt = g_cnt[n];
                const float inv = 1.0f / (cnt + 1e-6f);
                if (q == 0) sF[ng] = cnt * inv;
                const float4* xr = reinterpret_cast<const float4*>(x + (size_t)n * ND);
                const float4* ar = reinterpret_cast<const float4*>(g_agg + (size_t)n * HID);
#pragma unroll
                for (int i = 0; i < 4; i++) {
                    const int f4 = q + 4 * i;
                    const int k  = f4 * 4;
                    float4 v = xr[f4];
                    sIn[(k + 0) * TILE_N + ng] = v.x;
                    sIn[(k + 1) * TILE_N + ng] = v.y;
                    sIn[(k + 2) * TILE_N + ng] = v.z;
                    sIn[(k + 3) * TILE_N + ng] = v.w;
                    float4 w = ar[f4];
                    sIn[(ND + k + 0) * TILE_N + ng] = w.x * inv;
                    sIn[(ND + k + 1) * TILE_N + ng] = w.y * inv;
                    sIn[(ND + k + 2) * TILE_N + ng] = w.z * inv;
                    sIn[(ND + k + 3) * TILE_N + ng] = w.w * inv;
                }
            }
        }
        __syncthreads();

        float acc[4][4];
#pragma unroll
        for (int a = 0; a < 4; a++)
#pragma unroll
            for (int b = 0; b < 4; b++) acc[a][b] = 0.f;

#pragma unroll 8
        for (int k = 0; k < 2 * ND; k++) {
            float4 av = *reinterpret_cast<const float4*>(&sIn[k * TILE_N + tx * 4]);
            float4 bv = *reinterpret_cast<const float4*>(&sWu[k * HID + ty * 4]);
            FMA16(acc, av, bv)
        }

#pragma unroll
        for (int ei = 0; ei < 4; ei++) {
            const int n = n0 + tx * 4 + ei;
            if (n < N) {
                const float f = sF[tx * 4 + ei];
                float4 o;
                float r;
                r = acc[ei][0] + sBu[ty * 4 + 0] + f * sB2u[ty * 4 + 0];
                o.x = sIn[(ty * 4 + 0) * TILE_N + tx * 4 + ei] + (r > 0.f ? r : 0.f);
                r = acc[ei][1] + sBu[ty * 4 + 1] + f * sB2u[ty * 4 + 1];
                o.y = sIn[(ty * 4 + 1) * TILE_N + tx * 4 + ei] + (r > 0.f ? r : 0.f);
                r = acc[ei][2] + sBu[ty * 4 + 2] + f * sB2u[ty * 4 + 2];
                o.z = sIn[(ty * 4 + 2) * TILE_N + tx * 4 + ei] + (r > 0.f ? r : 0.f);
                r = acc[ei][3] + sBu[ty * 4 + 3] + f * sB2u[ty * 4 + 3];
                o.w = sIn[(ty * 4 + 3) * TILE_N + tx * 4 + ei] + (r > 0.f ? r : 0.f);
                *reinterpret_cast<float4*>(out + (size_t)n * HID + ty * 4) = o;
            }
        }
        __syncthreads();
    }
}

// ---------------------------------------------------------------------------
extern "C" void kernel_launch(void* const* d_in, const int* in_sizes, int n_in,
                              void* d_out, int out_size) {
    const float* x   = (const float*)d_in[0];
    const int*   ei  = (const int*)d_in[1];
    const float* ea  = (const float*)d_in[2];
    const float* W1  = (const float*)d_in[3];
    const float* b1  = (const float*)d_in[4];
    const float* W2  = (const float*)d_in[5];
    const float* b2  = (const float*)d_in[6];
    const float* Wu  = (const float*)d_in[7];
    const float* bu  = (const float*)d_in[8];
    float* out = (float*)d_out;

    const int N = in_sizes[0] / ND;     // 100000
    const int E = in_sizes[2] / EDIM;   // 1600000

    const int smem_pq   = (2 * 64 * LDW_H + 8 * 16 * LDX_H) * 2;
    const int smem_edge = 16 * LDW_H * 2 + 16 * 32 * LDIN_H * 2 + 512 * 4;
    const int smem_node = (2 * ND * HID + 2 * ND * TILE_N + 3 * HID) * 4;

    cudaFuncSetAttribute(pq_kernel, cudaFuncAttributeMaxDynamicSharedMemorySize,
                         smem_pq);
    cudaFuncSetAttribute(edge_kernel, cudaFuncAttributeMaxDynamicSharedMemorySize,
                         smem_edge);
    cudaFuncSetAttribute(node_kernel, cudaFuncAttributeMaxDynamicSharedMemorySize,
                         smem_node);

    const int npq = (N + 15) / 16;
    const int nst = (E + 15) / 16;
    const int ntiles = (N + TILE_N - 1) / TILE_N;

    zero_kernel<<<2048, 256>>>(N);
    w2u_kernel<<<(2 * ND * HID + HID + 255) / 256, 256>>>(W2, Wu, b2);
    pq_kernel<<<(npq + 7) / 8, 256, smem_pq>>>(x, W1, N, npq);
    edge_kernel<<<148, 512, smem_edge>>>(ei, ea, W1, b1, E, nst);
    node_kernel<<<456, 256, smem_node>>>(x, bu, out, N, ntiles);
}